// round 1
// baseline (speedup 1.0000x reference)
#include <cuda_runtime.h>
#include <cuda_bf16.h>
#include <math.h>

// Problem constants
#define BB 4
#define TT 2048
#define CC 1024
#define HH 16
#define DD 64
#define MROWS (BB * TT)          // 8192
#define C3 (3 * CC)              // 3072

// Scratch (device globals; no allocation allowed)
__device__ float g_qkv[(size_t)MROWS * C3];   // [B*T, 3C]  96 MB
__device__ float g_attn[(size_t)MROWS * CC];  // [B*T, C]   32 MB

// ---------------------------------------------------------------------------
// SGEMM: C[M,N] = A[M,K] @ B[K,N] + bias[N]
// BM=128, BN=128, BK=8, 256 threads, 8x8 per thread.
// M,N,K all multiples of tile dims (8192 x {3072,1024} x 1024) -> no bounds.
// ---------------------------------------------------------------------------
__global__ __launch_bounds__(256) void sgemm_bias_kernel(
    const float* __restrict__ A, const float* __restrict__ B,
    const float* __restrict__ bias, float* __restrict__ C,
    int M, int N, int K)
{
    const int BM = 128, BN = 128, BK = 8;
    __shared__ float As[BK][BM];
    __shared__ float Bs[BK][BN];

    const int tid  = threadIdx.x;
    const int brow = blockIdx.y * BM;
    const int bcol = blockIdx.x * BN;

    const int tr = (tid / 16) * 8;   // thread row within tile
    const int tc = (tid % 16) * 8;   // thread col within tile

    // A tile loader: 128 rows x 8 cols = 256 float4 (one per thread)
    const int arow = tid >> 1;
    const int acol = (tid & 1) * 4;
    // B tile loader: 8 rows x 128 cols = 256 float4
    const int brl = tid >> 5;
    const int bcl = (tid & 31) * 4;

    const float* Aptr = A + (size_t)brow * K;
    const float* Bptr = B + bcol;

    float acc[8][8];
    #pragma unroll
    for (int i = 0; i < 8; i++)
        #pragma unroll
        for (int j = 0; j < 8; j++) acc[i][j] = 0.f;

    for (int k0 = 0; k0 < K; k0 += BK) {
        float4 a4 = *(const float4*)(Aptr + (size_t)arow * K + k0 + acol);
        As[acol + 0][arow] = a4.x;
        As[acol + 1][arow] = a4.y;
        As[acol + 2][arow] = a4.z;
        As[acol + 3][arow] = a4.w;
        float4 b4 = *(const float4*)(Bptr + (size_t)(k0 + brl) * N + bcl);
        *(float4*)&Bs[brl][bcl] = b4;
        __syncthreads();

        #pragma unroll
        for (int kk = 0; kk < BK; kk++) {
            float4 a0 = *(float4*)&As[kk][tr];
            float4 a1 = *(float4*)&As[kk][tr + 4];
            float4 b0 = *(float4*)&Bs[kk][tc];
            float4 b1 = *(float4*)&Bs[kk][tc + 4];
            float ar[8] = {a0.x, a0.y, a0.z, a0.w, a1.x, a1.y, a1.z, a1.w};
            float br[8] = {b0.x, b0.y, b0.z, b0.w, b1.x, b1.y, b1.z, b1.w};
            #pragma unroll
            for (int i = 0; i < 8; i++)
                #pragma unroll
                for (int j = 0; j < 8; j++)
                    acc[i][j] = fmaf(ar[i], br[j], acc[i][j]);
        }
        __syncthreads();
    }

    #pragma unroll
    for (int i = 0; i < 8; i++) {
        float* cp = C + (size_t)(brow + tr + i) * N + bcol + tc;
        #pragma unroll
        for (int j = 0; j < 8; j += 4) {
            float4 o;
            o.x = acc[i][j + 0] + bias[bcol + tc + j + 0];
            o.y = acc[i][j + 1] + bias[bcol + tc + j + 1];
            o.z = acc[i][j + 2] + bias[bcol + tc + j + 2];
            o.w = acc[i][j + 3] + bias[bcol + tc + j + 3];
            *(float4*)(cp + j) = o;
        }
    }
}

// ---------------------------------------------------------------------------
// Causal flash attention, fp32.
// Grid: (T/128, H, B). 128 threads, one query row per thread.
// Q row + O accumulator in registers; K/V tiles (64x64) in shared;
// per-tile scores in padded shared (stride 65 -> conflict-free).
// qkv layout: [B*T, 3C]; q at col h*64, k at C + h*64, v at 2C + h*64.
// Output: g_attn[B*T, C] at col h*64 (i.e. [B,T,H,D] flattened = [B,T,C]).
// ---------------------------------------------------------------------------
#define ATTN_SMEM ((2 * 64 * 64 + 128 * 65) * 4)   // 66048 bytes

__global__ __launch_bounds__(128) void attn_kernel(
    const float* __restrict__ qkv, float* __restrict__ out)
{
    extern __shared__ float sm[];
    float* Ks = sm;                 // [64][64]
    float* Vs = sm + 64 * 64;       // [64][64]
    float* Ss = sm + 2 * 64 * 64;   // [128][65]

    const int tid = threadIdx.x;
    const int q0  = blockIdx.x * 128;
    const int h   = blockIdx.y;
    const int b   = blockIdx.z;
    const int qg  = q0 + tid;                      // global query index

    const size_t rs = C3;                          // row stride in qkv
    const float* qbase = qkv + (size_t)b * TT * rs + h * DD;
    const float* kbase = qbase + CC;
    const float* vbase = qbase + 2 * CC;

    // Load my Q row (64 floats) to registers
    float4 q4[16];
    {
        const float* qp = qbase + (size_t)qg * rs;
        #pragma unroll
        for (int i = 0; i < 16; i++) q4[i] = *(const float4*)(qp + i * 4);
    }

    const float scale = 0.125f * 1.44269504088896f;  // (1/sqrt(64)) * log2(e)
    float m = -1e30f, l = 0.f;
    float4 o4[16];
    #pragma unroll
    for (int i = 0; i < 16; i++) o4[i] = make_float4(0.f, 0.f, 0.f, 0.f);

    const int ntiles = q0 / 64 + 2;  // key tiles needed (causal)
    for (int t = 0; t < ntiles; t++) {
        const int k0 = t * 64;

        // Load K and V tiles: 64 rows x 64 cols, 8 float4 per thread per tile
        #pragma unroll
        for (int r = 0; r < 8; r++) {
            int idx = r * 128 + tid;         // 0..1023
            int row = idx >> 4;
            int c4  = (idx & 15) * 4;
            *(float4*)&Ks[row * 64 + c4] =
                *(const float4*)(kbase + (size_t)(k0 + row) * rs + c4);
            *(float4*)&Vs[row * 64 + c4] =
                *(const float4*)(vbase + (size_t)(k0 + row) * rs + c4);
        }
        __syncthreads();

        // Pass A: scores for my query row vs this key tile
        float tmax = -1e30f;
        #pragma unroll 4
        for (int k = 0; k < 64; k++) {
            const float4* kp = (const float4*)&Ks[k * 64];
            float s = 0.f;
            #pragma unroll
            for (int i = 0; i < 16; i++) {
                float4 kk = kp[i];
                s = fmaf(q4[i].x, kk.x, s);
                s = fmaf(q4[i].y, kk.y, s);
                s = fmaf(q4[i].z, kk.z, s);
                s = fmaf(q4[i].w, kk.w, s);
            }
            s *= scale;
            if (k0 + k > qg) s = -1e30f;     // causal mask
            tmax = fmaxf(tmax, s);
            Ss[tid * 65 + k] = s;
        }

        float mnew = fmaxf(m, tmax);
        float corr = exp2f(m - mnew);
        l *= corr;
        #pragma unroll
        for (int i = 0; i < 16; i++) {
            o4[i].x *= corr; o4[i].y *= corr;
            o4[i].z *= corr; o4[i].w *= corr;
        }

        // Pass B: accumulate P @ V
        #pragma unroll 2
        for (int k = 0; k < 64; k++) {
            float p = exp2f(Ss[tid * 65 + k] - mnew);
            l += p;
            const float4* vp = (const float4*)&Vs[k * 64];
            #pragma unroll
            for (int i = 0; i < 16; i++) {
                float4 v4 = vp[i];
                o4[i].x = fmaf(p, v4.x, o4[i].x);
                o4[i].y = fmaf(p, v4.y, o4[i].y);
                o4[i].z = fmaf(p, v4.z, o4[i].z);
                o4[i].w = fmaf(p, v4.w, o4[i].w);
            }
        }
        m = mnew;
        __syncthreads();
    }

    const float inv = 1.f / l;
    float* op = out + ((size_t)b * TT + qg) * CC + h * DD;
    #pragma unroll
    for (int i = 0; i < 16; i++) {
        float4 o = o4[i];
        o.x *= inv; o.y *= inv; o.z *= inv; o.w *= inv;
        *(float4*)(op + i * 4) = o;
    }
}

// ---------------------------------------------------------------------------
// Launch
// ---------------------------------------------------------------------------
extern "C" void kernel_launch(void* const* d_in, const int* in_sizes, int n_in,
                              void* d_out, int out_size)
{
    const float* x     = (const float*)d_in[0];   // [B,T,C]
    const float* W_qkv = (const float*)d_in[1];   // [C,3C]
    const float* b_qkv = (const float*)d_in[2];   // [3C]
    const float* W_out = (const float*)d_in[3];   // [C,C]
    const float* b_out = (const float*)d_in[4];   // [C]
    float* out = (float*)d_out;                   // [B,T,C]

    float* qkv  = nullptr;
    float* attn = nullptr;
    cudaGetSymbolAddress((void**)&qkv,  g_qkv);
    cudaGetSymbolAddress((void**)&attn, g_attn);

    // 1) QKV projection: [8192,1024] @ [1024,3072] + b_qkv
    {
        dim3 grid(C3 / 128, MROWS / 128);
        sgemm_bias_kernel<<<grid, 256>>>(x, W_qkv, b_qkv, qkv, MROWS, C3, CC);
    }

    // 2) Causal attention
    {
        cudaFuncSetAttribute(attn_kernel,
                             cudaFuncAttributeMaxDynamicSharedMemorySize,
                             ATTN_SMEM);
        dim3 grid(TT / 128, HH, BB);
        attn_kernel<<<grid, 128, ATTN_SMEM>>>(qkv, attn);
    }

    // 3) Output projection: [8192,1024] @ [1024,1024] + b_out
    {
        dim3 grid(CC / 128, MROWS / 128);
        sgemm_bias_kernel<<<grid, 256>>>(attn, W_out, b_out, out, MROWS, CC, CC);
    }
}

// round 6
// speedup vs baseline: 1.4831x; 1.4831x over previous
#include <cuda_runtime.h>
#include <cstdint>
#include <math.h>

// Problem constants
#define BB 4
#define TT 2048
#define CC 1024
#define HH 16
#define DD 64
#define MROWS (BB * TT)          // 8192
#define C3 (3 * CC)              // 3072

// Scratch (device globals; no allocation allowed)
__device__ float g_qkv[(size_t)MROWS * C3];    // [B*T, 3C]
__device__ float g_attn[(size_t)MROWS * CC];   // [B*T, C]
__device__ float g_wqkv_t[(size_t)C3 * CC];    // W_qkv^T  [3C, C]
__device__ float g_wout_t[(size_t)CC * CC];    // W_out^T  [C, C]

// ---------------------------------------------------------------------------
// tf32 helpers (portable PTX, works on plain sm_103 target)
// ---------------------------------------------------------------------------
__device__ __forceinline__ uint32_t f2tf32(float f) {
    uint32_t r;
    asm("cvt.rna.tf32.f32 %0, %1;" : "=r"(r) : "f"(f));
    return r;
}

__device__ __forceinline__ void mma_tf32_1688(
    float& c0, float& c1, float& c2, float& c3,
    uint32_t a0, uint32_t a1, uint32_t a2, uint32_t a3,
    uint32_t b0, uint32_t b1)
{
    asm volatile(
        "mma.sync.aligned.m16n8k8.row.col.f32.tf32.tf32.f32 "
        "{%0,%1,%2,%3}, {%4,%5,%6,%7}, {%8,%9}, {%0,%1,%2,%3};"
        : "+f"(c0), "+f"(c1), "+f"(c2), "+f"(c3)
        : "r"(a0), "r"(a1), "r"(a2), "r"(a3), "r"(b0), "r"(b1));
}

// ---------------------------------------------------------------------------
// tf32 mma.sync GEMM:  C[M,N] = A[M,K] @ Bt[N,K]^T + bias[N]
// A row-major [M,K]; Bt row-major [N,K] (pre-transposed weights).
// Block 128x128, BK=16, 256 threads = 8 warps, warp tile 64x32
// (4 m-tiles x 4 n-tiles of m16n8k8). Double-buffered smem, stride-20 pad
// (conflict-free for the 8-row x 4-col fragment lane pattern).
// ---------------------------------------------------------------------------
#define PAD 20   // floats per smem row (16 + 4)

__global__ __launch_bounds__(256) void gemm_mma_tf32(
    const float* __restrict__ A, const float* __restrict__ Bt,
    const float* __restrict__ bias, float* __restrict__ C,
    int M, int N, int K)
{
    __shared__ uint32_t As[2][128 * PAD];
    __shared__ uint32_t Bs[2][128 * PAD];

    const int tid = threadIdx.x;
    const int wid = tid >> 5;
    const int lane = tid & 31;
    const int g   = lane >> 2;     // groupID   (0..7)
    const int tig = lane & 3;      // thread in group (0..3)

    const int wr = wid >> 2;       // warp row (0..1) -> 64 rows each
    const int wc = wid & 3;        // warp col (0..3) -> 32 cols each

    const int brow = blockIdx.y * 128;
    const int bcol = blockIdx.x * 128;

    // G->S loader coords: 128 rows x 16 cols = 512 float4; 2 per thread
    const int lrow = tid >> 2;         // 0..63  (also lrow+64)
    const int lc4  = (tid & 3) * 4;    // 0,4,8,12

    const float* Ab = A + (size_t)brow * K;
    const float* Bb = Bt + (size_t)bcol * K;

    float acc[4][4][4];
    #pragma unroll
    for (int mi = 0; mi < 4; mi++)
        #pragma unroll
        for (int ni = 0; ni < 4; ni++)
            #pragma unroll
            for (int r = 0; r < 4; r++) acc[mi][ni][r] = 0.f;

    const int niter = K / 16;

    // Preload iter 0 into buffer 0
    {
        float4 a0 = *(const float4*)(Ab + (size_t)lrow * K + lc4);
        float4 a1 = *(const float4*)(Ab + (size_t)(lrow + 64) * K + lc4);
        float4 b0 = *(const float4*)(Bb + (size_t)lrow * K + lc4);
        float4 b1 = *(const float4*)(Bb + (size_t)(lrow + 64) * K + lc4);
        uint4 ua0 = make_uint4(f2tf32(a0.x), f2tf32(a0.y), f2tf32(a0.z), f2tf32(a0.w));
        uint4 ua1 = make_uint4(f2tf32(a1.x), f2tf32(a1.y), f2tf32(a1.z), f2tf32(a1.w));
        uint4 ub0 = make_uint4(f2tf32(b0.x), f2tf32(b0.y), f2tf32(b0.z), f2tf32(b0.w));
        uint4 ub1 = make_uint4(f2tf32(b1.x), f2tf32(b1.y), f2tf32(b1.z), f2tf32(b1.w));
        *(uint4*)&As[0][lrow * PAD + lc4]        = ua0;
        *(uint4*)&As[0][(lrow + 64) * PAD + lc4] = ua1;
        *(uint4*)&Bs[0][lrow * PAD + lc4]        = ub0;
        *(uint4*)&Bs[0][(lrow + 64) * PAD + lc4] = ub1;
    }
    __syncthreads();

    for (int it = 0; it < niter; it++) {
        const int buf = it & 1;
        const bool has_next = (it + 1) < niter;

        float4 pa0, pa1, pb0, pb1;
        if (has_next) {
            const int k0 = (it + 1) * 16;
            pa0 = *(const float4*)(Ab + (size_t)lrow * K + k0 + lc4);
            pa1 = *(const float4*)(Ab + (size_t)(lrow + 64) * K + k0 + lc4);
            pb0 = *(const float4*)(Bb + (size_t)lrow * K + k0 + lc4);
            pb1 = *(const float4*)(Bb + (size_t)(lrow + 64) * K + k0 + lc4);
        }

        const uint32_t* Ac = As[buf];
        const uint32_t* Bc = Bs[buf];

        #pragma unroll
        for (int ks = 0; ks < 2; ks++) {
            const int kb = ks * 8;
            uint32_t af[4][4];
            uint32_t bf[4][2];
            #pragma unroll
            for (int mi = 0; mi < 4; mi++) {
                const int rb = wr * 64 + mi * 16;
                af[mi][0] = Ac[(rb + g) * PAD + kb + tig];
                af[mi][1] = Ac[(rb + g + 8) * PAD + kb + tig];
                af[mi][2] = Ac[(rb + g) * PAD + kb + tig + 4];
                af[mi][3] = Ac[(rb + g + 8) * PAD + kb + tig + 4];
            }
            #pragma unroll
            for (int ni = 0; ni < 4; ni++) {
                const int nb = wc * 32 + ni * 8;
                bf[ni][0] = Bc[(nb + g) * PAD + kb + tig];
                bf[ni][1] = Bc[(nb + g) * PAD + kb + tig + 4];
            }
            #pragma unroll
            for (int mi = 0; mi < 4; mi++)
                #pragma unroll
                for (int ni = 0; ni < 4; ni++)
                    mma_tf32_1688(acc[mi][ni][0], acc[mi][ni][1],
                                  acc[mi][ni][2], acc[mi][ni][3],
                                  af[mi][0], af[mi][1], af[mi][2], af[mi][3],
                                  bf[ni][0], bf[ni][1]);
        }

        if (has_next) {
            const int nbuf = buf ^ 1;
            uint4 ua0 = make_uint4(f2tf32(pa0.x), f2tf32(pa0.y), f2tf32(pa0.z), f2tf32(pa0.w));
            uint4 ua1 = make_uint4(f2tf32(pa1.x), f2tf32(pa1.y), f2tf32(pa1.z), f2tf32(pa1.w));
            uint4 ub0 = make_uint4(f2tf32(pb0.x), f2tf32(pb0.y), f2tf32(pb0.z), f2tf32(pb0.w));
            uint4 ub1 = make_uint4(f2tf32(pb1.x), f2tf32(pb1.y), f2tf32(pb1.z), f2tf32(pb1.w));
            *(uint4*)&As[nbuf][lrow * PAD + lc4]        = ua0;
            *(uint4*)&As[nbuf][(lrow + 64) * PAD + lc4] = ua1;
            *(uint4*)&Bs[nbuf][lrow * PAD + lc4]        = ub0;
            *(uint4*)&Bs[nbuf][(lrow + 64) * PAD + lc4] = ub1;
        }
        __syncthreads();
    }

    // Epilogue: c0:(row+g, col+2t) c1:(+1) c2:(row+8) c3:(row+8,+1)
    #pragma unroll
    for (int mi = 0; mi < 4; mi++) {
        const int row0 = brow + wr * 64 + mi * 16 + g;
        #pragma unroll
        for (int ni = 0; ni < 4; ni++) {
            const int col0 = bcol + wc * 32 + ni * 8 + 2 * tig;
            const float bx = bias[col0], by = bias[col0 + 1];
            float2 lo = make_float2(acc[mi][ni][0] + bx, acc[mi][ni][1] + by);
            float2 hi = make_float2(acc[mi][ni][2] + bx, acc[mi][ni][3] + by);
            *(float2*)(C + (size_t)row0 * N + col0) = lo;
            *(float2*)(C + (size_t)(row0 + 8) * N + col0) = hi;
        }
    }
}

// ---------------------------------------------------------------------------
// 32x32 tiled transpose: Wt[c][r] = W[r][c].  W is [R, Ccols].
// ---------------------------------------------------------------------------
__global__ void transpose_kernel(const float* __restrict__ W, float* __restrict__ Wt,
                                 int R, int Ccols)
{
    __shared__ float t[32][33];
    int bx = blockIdx.x * 32, by = blockIdx.y * 32;
    int x = bx + threadIdx.x;
    #pragma unroll
    for (int j = 0; j < 32; j += 8)
        t[threadIdx.y + j][threadIdx.x] = W[(size_t)(by + threadIdx.y + j) * Ccols + x];
    __syncthreads();
    int xo = by + threadIdx.x;
    #pragma unroll
    for (int j = 0; j < 32; j += 8)
        Wt[(size_t)(bx + threadIdx.y + j) * R + xo] = t[threadIdx.x][threadIdx.y + j];
}

// ---------------------------------------------------------------------------
// Causal flash attention, fp32 (known-good from round 0).
// ---------------------------------------------------------------------------
#define ATTN_SMEM ((2 * 64 * 64 + 128 * 65) * 4)

__global__ __launch_bounds__(128) void attn_kernel(
    const float* __restrict__ qkv, float* __restrict__ out)
{
    extern __shared__ float sm[];
    float* Ks = sm;
    float* Vs = sm + 64 * 64;
    float* Ss = sm + 2 * 64 * 64;

    const int tid = threadIdx.x;
    const int q0  = blockIdx.x * 128;
    const int h   = blockIdx.y;
    const int b   = blockIdx.z;
    const int qg  = q0 + tid;

    const size_t rs = C3;
    const float* qbase = qkv + (size_t)b * TT * rs + h * DD;
    const float* kbase = qbase + CC;
    const float* vbase = qbase + 2 * CC;

    float4 q4[16];
    {
        const float* qp = qbase + (size_t)qg * rs;
        #pragma unroll
        for (int i = 0; i < 16; i++) q4[i] = *(const float4*)(qp + i * 4);
    }

    const float scale = 0.125f * 1.44269504088896f;
    float m = -1e30f, l = 0.f;
    float4 o4[16];
    #pragma unroll
    for (int i = 0; i < 16; i++) o4[i] = make_float4(0.f, 0.f, 0.f, 0.f);

    const int ntiles = q0 / 64 + 2;
    for (int t = 0; t < ntiles; t++) {
        const int k0 = t * 64;
        #pragma unroll
        for (int r = 0; r < 8; r++) {
            int idx = r * 128 + tid;
            int row = idx >> 4;
            int c4  = (idx & 15) * 4;
            *(float4*)&Ks[row * 64 + c4] =
                *(const float4*)(kbase + (size_t)(k0 + row) * rs + c4);
            *(float4*)&Vs[row * 64 + c4] =
                *(const float4*)(vbase + (size_t)(k0 + row) * rs + c4);
        }
        __syncthreads();

        float tmax = -1e30f;
        #pragma unroll 4
        for (int k = 0; k < 64; k++) {
            const float4* kp = (const float4*)&Ks[k * 64];
            float s = 0.f;
            #pragma unroll
            for (int i = 0; i < 16; i++) {
                float4 kk = kp[i];
                s = fmaf(q4[i].x, kk.x, s);
                s = fmaf(q4[i].y, kk.y, s);
                s = fmaf(q4[i].z, kk.z, s);
                s = fmaf(q4[i].w, kk.w, s);
            }
            s *= scale;
            if (k0 + k > qg) s = -1e30f;
            tmax = fmaxf(tmax, s);
            Ss[tid * 65 + k] = s;
        }

        float mnew = fmaxf(m, tmax);
        float corr = exp2f(m - mnew);
        l *= corr;
        #pragma unroll
        for (int i = 0; i < 16; i++) {
            o4[i].x *= corr; o4[i].y *= corr;
            o4[i].z *= corr; o4[i].w *= corr;
        }

        #pragma unroll 2
        for (int k = 0; k < 64; k++) {
            float p = exp2f(Ss[tid * 65 + k] - mnew);
            l += p;
            const float4* vp = (const float4*)&Vs[k * 64];
            #pragma unroll
            for (int i = 0; i < 16; i++) {
                float4 v4 = vp[i];
                o4[i].x = fmaf(p, v4.x, o4[i].x);
                o4[i].y = fmaf(p, v4.y, o4[i].y);
                o4[i].z = fmaf(p, v4.z, o4[i].z);
                o4[i].w = fmaf(p, v4.w, o4[i].w);
            }
        }
        m = mnew;
        __syncthreads();
    }

    const float inv = 1.f / l;
    float* op = out + ((size_t)b * TT + qg) * CC + h * DD;
    #pragma unroll
    for (int i = 0; i < 16; i++) {
        float4 o = o4[i];
        o.x *= inv; o.y *= inv; o.z *= inv; o.w *= inv;
        *(float4*)(op + i * 4) = o;
    }
}

// ---------------------------------------------------------------------------
// Launch
// ---------------------------------------------------------------------------
extern "C" void kernel_launch(void* const* d_in, const int* in_sizes, int n_in,
                              void* d_out, int out_size)
{
    const float* x     = (const float*)d_in[0];
    const float* W_qkv = (const float*)d_in[1];
    const float* b_qkv = (const float*)d_in[2];
    const float* W_out = (const float*)d_in[3];
    const float* b_out = (const float*)d_in[4];
    float* out = (float*)d_out;

    float *qkv = nullptr, *attn = nullptr, *wqkv_t = nullptr, *wout_t = nullptr;
    cudaGetSymbolAddress((void**)&qkv,    g_qkv);
    cudaGetSymbolAddress((void**)&attn,   g_attn);
    cudaGetSymbolAddress((void**)&wqkv_t, g_wqkv_t);
    cudaGetSymbolAddress((void**)&wout_t, g_wout_t);

    cudaFuncSetAttribute(attn_kernel,
                         cudaFuncAttributeMaxDynamicSharedMemorySize, ATTN_SMEM);

    // 0) Transpose weights: W_qkv [C,3C] -> [3C,C], W_out [C,C] -> [C,C]
    {
        dim3 blk(32, 8);
        transpose_kernel<<<dim3(C3 / 32, CC / 32), blk>>>(W_qkv, wqkv_t, CC, C3);
        transpose_kernel<<<dim3(CC / 32, CC / 32), blk>>>(W_out, wout_t, CC, CC);
    }

    // 1) QKV projection: [8192,1024] @ [1024,3072] + b_qkv (tf32 mma.sync)
    {
        dim3 grid(C3 / 128, MROWS / 128);
        gemm_mma_tf32<<<grid, 256>>>(x, wqkv_t, b_qkv, qkv, MROWS, C3, CC);
    }

    // 2) Causal attention (fp32 SIMT)
    {
        dim3 grid(TT / 128, HH, BB);
        attn_kernel<<<grid, 128, ATTN_SMEM>>>(qkv, attn);
    }

    // 3) Output projection: [8192,1024] @ [1024,1024] + b_out (tf32 mma.sync)
    {
        dim3 grid(CC / 128, MROWS / 128);
        gemm_mma_tf32<<<grid, 256>>>(attn, wout_t, b_out, out, MROWS, CC, CC);
    }
}

// round 8
// speedup vs baseline: 3.3339x; 2.2479x over previous
#include <cuda_runtime.h>
#include <cstdint>
#include <math.h>

// Problem constants
#define BB 4
#define TT 2048
#define CC 1024
#define HH 16
#define DD 64
#define MROWS (BB * TT)          // 8192
#define C3 (3 * CC)              // 3072

// Scratch (device globals; no allocation allowed)
__device__ float g_qkv[(size_t)MROWS * C3];    // [B*T, 3C]
__device__ float g_attn[(size_t)MROWS * CC];   // [B*T, C]
__device__ float g_wqkv_t[(size_t)C3 * CC];    // W_qkv^T  [3C, C]
__device__ float g_wout_t[(size_t)CC * CC];    // W_out^T  [C, C]

// ---------------------------------------------------------------------------
// tf32 helpers (portable PTX, works on plain sm_103 target)
// ---------------------------------------------------------------------------
__device__ __forceinline__ uint32_t f2tf32(float f) {
    uint32_t r;
    asm("cvt.rna.tf32.f32 %0, %1;" : "=r"(r) : "f"(f));
    return r;
}

__device__ __forceinline__ void mma_tf32_1688(
    float& c0, float& c1, float& c2, float& c3,
    uint32_t a0, uint32_t a1, uint32_t a2, uint32_t a3,
    uint32_t b0, uint32_t b1)
{
    asm volatile(
        "mma.sync.aligned.m16n8k8.row.col.f32.tf32.tf32.f32 "
        "{%0,%1,%2,%3}, {%4,%5,%6,%7}, {%8,%9}, {%0,%1,%2,%3};"
        : "+f"(c0), "+f"(c1), "+f"(c2), "+f"(c3)
        : "r"(a0), "r"(a1), "r"(a2), "r"(a3), "r"(b0), "r"(b1));
}

// ---------------------------------------------------------------------------
// tf32 mma.sync GEMM:  C[M,N] = A[M,K] @ Bt[N,K]^T + bias[N]   (validated R6)
// ---------------------------------------------------------------------------
#define PAD 20   // floats per smem row (16 + 4)

__global__ __launch_bounds__(256) void gemm_mma_tf32(
    const float* __restrict__ A, const float* __restrict__ Bt,
    const float* __restrict__ bias, float* __restrict__ C,
    int M, int N, int K)
{
    __shared__ uint32_t As[2][128 * PAD];
    __shared__ uint32_t Bs[2][128 * PAD];

    const int tid = threadIdx.x;
    const int wid = tid >> 5;
    const int lane = tid & 31;
    const int g   = lane >> 2;
    const int tig = lane & 3;

    const int wr = wid >> 2;
    const int wc = wid & 3;

    const int brow = blockIdx.y * 128;
    const int bcol = blockIdx.x * 128;

    const int lrow = tid >> 2;
    const int lc4  = (tid & 3) * 4;

    const float* Ab = A + (size_t)brow * K;
    const float* Bb = Bt + (size_t)bcol * K;

    float acc[4][4][4];
    #pragma unroll
    for (int mi = 0; mi < 4; mi++)
        #pragma unroll
        for (int ni = 0; ni < 4; ni++)
            #pragma unroll
            for (int r = 0; r < 4; r++) acc[mi][ni][r] = 0.f;

    const int niter = K / 16;

    {
        float4 a0 = *(const float4*)(Ab + (size_t)lrow * K + lc4);
        float4 a1 = *(const float4*)(Ab + (size_t)(lrow + 64) * K + lc4);
        float4 b0 = *(const float4*)(Bb + (size_t)lrow * K + lc4);
        float4 b1 = *(const float4*)(Bb + (size_t)(lrow + 64) * K + lc4);
        uint4 ua0 = make_uint4(f2tf32(a0.x), f2tf32(a0.y), f2tf32(a0.z), f2tf32(a0.w));
        uint4 ua1 = make_uint4(f2tf32(a1.x), f2tf32(a1.y), f2tf32(a1.z), f2tf32(a1.w));
        uint4 ub0 = make_uint4(f2tf32(b0.x), f2tf32(b0.y), f2tf32(b0.z), f2tf32(b0.w));
        uint4 ub1 = make_uint4(f2tf32(b1.x), f2tf32(b1.y), f2tf32(b1.z), f2tf32(b1.w));
        *(uint4*)&As[0][lrow * PAD + lc4]        = ua0;
        *(uint4*)&As[0][(lrow + 64) * PAD + lc4] = ua1;
        *(uint4*)&Bs[0][lrow * PAD + lc4]        = ub0;
        *(uint4*)&Bs[0][(lrow + 64) * PAD + lc4] = ub1;
    }
    __syncthreads();

    for (int it = 0; it < niter; it++) {
        const int buf = it & 1;
        const bool has_next = (it + 1) < niter;

        float4 pa0, pa1, pb0, pb1;
        if (has_next) {
            const int k0 = (it + 1) * 16;
            pa0 = *(const float4*)(Ab + (size_t)lrow * K + k0 + lc4);
            pa1 = *(const float4*)(Ab + (size_t)(lrow + 64) * K + k0 + lc4);
            pb0 = *(const float4*)(Bb + (size_t)lrow * K + k0 + lc4);
            pb1 = *(const float4*)(Bb + (size_t)(lrow + 64) * K + k0 + lc4);
        }

        const uint32_t* Ac = As[buf];
        const uint32_t* Bc = Bs[buf];

        #pragma unroll
        for (int ks = 0; ks < 2; ks++) {
            const int kb = ks * 8;
            uint32_t af[4][4];
            uint32_t bf[4][2];
            #pragma unroll
            for (int mi = 0; mi < 4; mi++) {
                const int rb = wr * 64 + mi * 16;
                af[mi][0] = Ac[(rb + g) * PAD + kb + tig];
                af[mi][1] = Ac[(rb + g + 8) * PAD + kb + tig];
                af[mi][2] = Ac[(rb + g) * PAD + kb + tig + 4];
                af[mi][3] = Ac[(rb + g + 8) * PAD + kb + tig + 4];
            }
            #pragma unroll
            for (int ni = 0; ni < 4; ni++) {
                const int nb = wc * 32 + ni * 8;
                bf[ni][0] = Bc[(nb + g) * PAD + kb + tig];
                bf[ni][1] = Bc[(nb + g) * PAD + kb + tig + 4];
            }
            #pragma unroll
            for (int mi = 0; mi < 4; mi++)
                #pragma unroll
                for (int ni = 0; ni < 4; ni++)
                    mma_tf32_1688(acc[mi][ni][0], acc[mi][ni][1],
                                  acc[mi][ni][2], acc[mi][ni][3],
                                  af[mi][0], af[mi][1], af[mi][2], af[mi][3],
                                  bf[ni][0], bf[ni][1]);
        }

        if (has_next) {
            const int nbuf = buf ^ 1;
            uint4 ua0 = make_uint4(f2tf32(pa0.x), f2tf32(pa0.y), f2tf32(pa0.z), f2tf32(pa0.w));
            uint4 ua1 = make_uint4(f2tf32(pa1.x), f2tf32(pa1.y), f2tf32(pa1.z), f2tf32(pa1.w));
            uint4 ub0 = make_uint4(f2tf32(pb0.x), f2tf32(pb0.y), f2tf32(pb0.z), f2tf32(pb0.w));
            uint4 ub1 = make_uint4(f2tf32(pb1.x), f2tf32(pb1.y), f2tf32(pb1.z), f2tf32(pb1.w));
            *(uint4*)&As[nbuf][lrow * PAD + lc4]        = ua0;
            *(uint4*)&As[nbuf][(lrow + 64) * PAD + lc4] = ua1;
            *(uint4*)&Bs[nbuf][lrow * PAD + lc4]        = ub0;
            *(uint4*)&Bs[nbuf][(lrow + 64) * PAD + lc4] = ub1;
        }
        __syncthreads();
    }

    #pragma unroll
    for (int mi = 0; mi < 4; mi++) {
        const int row0 = brow + wr * 64 + mi * 16 + g;
        #pragma unroll
        for (int ni = 0; ni < 4; ni++) {
            const int col0 = bcol + wc * 32 + ni * 8 + 2 * tig;
            const float bx = bias[col0], by = bias[col0 + 1];
            float2 lo = make_float2(acc[mi][ni][0] + bx, acc[mi][ni][1] + by);
            float2 hi = make_float2(acc[mi][ni][2] + bx, acc[mi][ni][3] + by);
            *(float2*)(C + (size_t)row0 * N + col0) = lo;
            *(float2*)(C + (size_t)(row0 + 8) * N + col0) = hi;
        }
    }
}

// ---------------------------------------------------------------------------
// 32x32 tiled transpose
// ---------------------------------------------------------------------------
__global__ void transpose_kernel(const float* __restrict__ W, float* __restrict__ Wt,
                                 int R, int Ccols)
{
    __shared__ float t[32][33];
    int bx = blockIdx.x * 32, by = blockIdx.y * 32;
    int x = bx + threadIdx.x;
    #pragma unroll
    for (int j = 0; j < 32; j += 8)
        t[threadIdx.y + j][threadIdx.x] = W[(size_t)(by + threadIdx.y + j) * Ccols + x];
    __syncthreads();
    int xo = by + threadIdx.x;
    #pragma unroll
    for (int j = 0; j < 32; j += 8)
        Wt[(size_t)(bx + threadIdx.y + j) * R + xo] = t[threadIdx.x][threadIdx.y + j];
}

// ---------------------------------------------------------------------------
// Causal flash attention on tf32 mma.sync.
// Block = 128 queries x (b,h). 256 threads = 8 warps; warp w owns query rows
// [w*16, w*16+16). Key tiles of 64. Q fragments live in registers.
// Smem (uint32/tf32): Ks[64][68] K-major; Vt[64][68] = V^T [d][key] with
// key ^ ((d>>2)&3) swizzle; Ss[128][68] = Q staging, then P per-warp strips.
// ---------------------------------------------------------------------------
#define AT_PAD 68
#define AT_KS 0
#define AT_VT (64 * AT_PAD)
#define AT_SS (2 * 64 * AT_PAD)
#define ATTN_SMEM ((2 * 64 * AT_PAD + 128 * AT_PAD) * 4)   // 69632 bytes

__global__ __launch_bounds__(256) void attn_mma_kernel(
    const float* __restrict__ qkv, float* __restrict__ out)
{
    extern __shared__ uint32_t sm[];
    uint32_t* Ks = sm + AT_KS;
    uint32_t* Vt = sm + AT_VT;
    uint32_t* Ss = sm + AT_SS;

    const int tid = threadIdx.x;
    const int wid = tid >> 5;
    const int lane = tid & 31;
    const int g = lane >> 2;
    const int tig = lane & 3;
    const int q0 = blockIdx.x * 128;
    const int h = blockIdx.y;
    const int b = blockIdx.z;

    const size_t rs = C3;
    const float* qbase = qkv + (size_t)b * TT * rs + h * DD;
    const float* kbase = qbase + CC;
    const float* vbase = qbase + 2 * CC;

    // loader coords: 16 rows x 64 cols per sweep (256 threads)
    const int lrow = tid >> 4;        // 0..15
    const int lc4  = (tid & 15) * 4;  // 0..60

    // ---- Stage Q tile (128x64) into Ss as tf32, build A-fragments in regs
    #pragma unroll
    for (int r = 0; r < 8; r++) {
        int row = r * 16 + lrow;
        float4 v = *(const float4*)(qbase + (size_t)(q0 + row) * rs + lc4);
        uint32_t* d = &Ss[row * AT_PAD + lc4];
        d[0] = f2tf32(v.x); d[1] = f2tf32(v.y);
        d[2] = f2tf32(v.z); d[3] = f2tf32(v.w);
    }
    __syncthreads();

    uint32_t qf[8][4];
    {
        const uint32_t* qs = &Ss[(wid * 16) * AT_PAD];
        #pragma unroll
        for (int ks = 0; ks < 8; ks++) {
            qf[ks][0] = qs[g * AT_PAD + ks * 8 + tig];
            qf[ks][1] = qs[(g + 8) * AT_PAD + ks * 8 + tig];
            qf[ks][2] = qs[g * AT_PAD + ks * 8 + tig + 4];
            qf[ks][3] = qs[(g + 8) * AT_PAD + ks * 8 + tig + 4];
        }
    }
    __syncthreads();   // Ss now free for P strips

    float of[8][4];
    #pragma unroll
    for (int nf = 0; nf < 8; nf++)
        #pragma unroll
        for (int r = 0; r < 4; r++) of[nf][r] = 0.f;

    float m_lo = -1e30f, m_hi = -1e30f, l_lo = 0.f, l_hi = 0.f;
    const float sc = 0.125f * 1.44269504088896f;   // scale * log2(e)
    const int nt = q0 / 64 + 2;
    const int qlo = q0 + wid * 16 + g;
    const int qhi = qlo + 8;

    uint32_t* ps = &Ss[(wid * 16) * AT_PAD];   // this warp's P strip

    for (int t = 0; t < nt; t++) {
        const int k0 = t * 64;

        // ---- load K tile (K-major) and V tile (transposed+swizzled), tf32
        #pragma unroll
        for (int r = 0; r < 4; r++) {
            int row = r * 16 + lrow;   // key index 0..63
            float4 kv = *(const float4*)(kbase + (size_t)(k0 + row) * rs + lc4);
            uint32_t* kd = &Ks[row * AT_PAD + lc4];
            kd[0] = f2tf32(kv.x); kd[1] = f2tf32(kv.y);
            kd[2] = f2tf32(kv.z); kd[3] = f2tf32(kv.w);
            float4 vv = *(const float4*)(vbase + (size_t)(k0 + row) * rs + lc4);
            float vs[4] = {vv.x, vv.y, vv.z, vv.w};
            #pragma unroll
            for (int i = 0; i < 4; i++) {
                int d = lc4 + i;
                Vt[d * AT_PAD + (row ^ ((d >> 2) & 3))] = f2tf32(vs[i]);
            }
        }
        __syncthreads();

        const bool skip = (t == nt - 1) && (wid < 4);
        if (!skip) {
            // ---- S = Q @ K^T  (16q x 64k per warp)
            float sf[8][4];
            #pragma unroll
            for (int nf = 0; nf < 8; nf++)
                #pragma unroll
                for (int r = 0; r < 4; r++) sf[nf][r] = 0.f;

            #pragma unroll
            for (int ks = 0; ks < 8; ks++) {
                #pragma unroll
                for (int nf = 0; nf < 8; nf++) {
                    uint32_t b0 = Ks[(nf * 8 + g) * AT_PAD + ks * 8 + tig];
                    uint32_t b1 = Ks[(nf * 8 + g) * AT_PAD + ks * 8 + tig + 4];
                    mma_tf32_1688(sf[nf][0], sf[nf][1], sf[nf][2], sf[nf][3],
                                  qf[ks][0], qf[ks][1], qf[ks][2], qf[ks][3],
                                  b0, b1);
                }
            }

            // ---- scale + causal mask + tile max
            const bool diag = (t == nt - 1) || (t == nt - 2 && wid < 4);
            float tmax_lo = -1e30f, tmax_hi = -1e30f;
            #pragma unroll
            for (int nf = 0; nf < 8; nf++) {
                int kg = k0 + nf * 8 + 2 * tig;
                float s0 = sf[nf][0] * sc, s1 = sf[nf][1] * sc;
                float s2 = sf[nf][2] * sc, s3 = sf[nf][3] * sc;
                if (diag) {
                    if (kg     > qlo) s0 = -1e30f;
                    if (kg + 1 > qlo) s1 = -1e30f;
                    if (kg     > qhi) s2 = -1e30f;
                    if (kg + 1 > qhi) s3 = -1e30f;
                }
                sf[nf][0] = s0; sf[nf][1] = s1; sf[nf][2] = s2; sf[nf][3] = s3;
                tmax_lo = fmaxf(tmax_lo, fmaxf(s0, s1));
                tmax_hi = fmaxf(tmax_hi, fmaxf(s2, s3));
            }
            tmax_lo = fmaxf(tmax_lo, __shfl_xor_sync(0xFFFFFFFFu, tmax_lo, 1));
            tmax_lo = fmaxf(tmax_lo, __shfl_xor_sync(0xFFFFFFFFu, tmax_lo, 2));
            tmax_hi = fmaxf(tmax_hi, __shfl_xor_sync(0xFFFFFFFFu, tmax_hi, 1));
            tmax_hi = fmaxf(tmax_hi, __shfl_xor_sync(0xFFFFFFFFu, tmax_hi, 2));

            const float mn_lo = fmaxf(m_lo, tmax_lo);
            const float mn_hi = fmaxf(m_hi, tmax_hi);
            const float corr_lo = exp2f(m_lo - mn_lo);
            const float corr_hi = exp2f(m_hi - mn_hi);
            m_lo = mn_lo; m_hi = mn_hi;
            l_lo *= corr_lo; l_hi *= corr_hi;
            #pragma unroll
            for (int nf = 0; nf < 8; nf++) {
                of[nf][0] *= corr_lo; of[nf][1] *= corr_lo;
                of[nf][2] *= corr_hi; of[nf][3] *= corr_hi;
            }

            // ---- P = exp2(S - m); store tf32 P strip; accumulate l
            #pragma unroll
            for (int nf = 0; nf < 8; nf++) {
                float p0 = exp2f(sf[nf][0] - mn_lo);
                float p1 = exp2f(sf[nf][1] - mn_lo);
                float p2 = exp2f(sf[nf][2] - mn_hi);
                float p3 = exp2f(sf[nf][3] - mn_hi);
                l_lo += p0 + p1;
                l_hi += p2 + p3;
                uint2 plo = make_uint2(f2tf32(p0), f2tf32(p1));
                uint2 phi = make_uint2(f2tf32(p2), f2tf32(p3));
                *(uint2*)&ps[g * AT_PAD + nf * 8 + 2 * tig] = plo;
                *(uint2*)&ps[(g + 8) * AT_PAD + nf * 8 + 2 * tig] = phi;
            }
            __syncwarp();

            // ---- O += P @ V   (V^T fragments from Vt)
            #pragma unroll
            for (int ks = 0; ks < 8; ks++) {       // key groups of 8
                uint32_t a0 = ps[g * AT_PAD + ks * 8 + tig];
                uint32_t a1 = ps[(g + 8) * AT_PAD + ks * 8 + tig];
                uint32_t a2 = ps[g * AT_PAD + ks * 8 + tig + 4];
                uint32_t a3 = ps[(g + 8) * AT_PAD + ks * 8 + tig + 4];
                #pragma unroll
                for (int nf = 0; nf < 8; nf++) {   // d groups of 8
                    int drow = nf * 8 + g;
                    int f = (drow >> 2) & 3;
                    uint32_t b0 = Vt[drow * AT_PAD + ((ks * 8 + tig) ^ f)];
                    uint32_t b1 = Vt[drow * AT_PAD + ((ks * 8 + tig + 4) ^ f)];
                    mma_tf32_1688(of[nf][0], of[nf][1], of[nf][2], of[nf][3],
                                  a0, a1, a2, a3, b0, b1);
                }
            }
        }
        __syncthreads();
    }

    // ---- finalize: quad-reduce l, divide, write out [B,T,H,D]
    l_lo += __shfl_xor_sync(0xFFFFFFFFu, l_lo, 1);
    l_lo += __shfl_xor_sync(0xFFFFFFFFu, l_lo, 2);
    l_hi += __shfl_xor_sync(0xFFFFFFFFu, l_hi, 1);
    l_hi += __shfl_xor_sync(0xFFFFFFFFu, l_hi, 2);
    const float inv_lo = 1.f / l_lo;
    const float inv_hi = 1.f / l_hi;

    float* olo = out + ((size_t)b * TT + qlo) * CC + h * DD;
    float* ohi = out + ((size_t)b * TT + qhi) * CC + h * DD;
    #pragma unroll
    for (int nf = 0; nf < 8; nf++) {
        float2 lo = make_float2(of[nf][0] * inv_lo, of[nf][1] * inv_lo);
        float2 hi = make_float2(of[nf][2] * inv_hi, of[nf][3] * inv_hi);
        *(float2*)(olo + nf * 8 + 2 * tig) = lo;
        *(float2*)(ohi + nf * 8 + 2 * tig) = hi;
    }
}

// ---------------------------------------------------------------------------
// Launch
// ---------------------------------------------------------------------------
extern "C" void kernel_launch(void* const* d_in, const int* in_sizes, int n_in,
                              void* d_out, int out_size)
{
    const float* x     = (const float*)d_in[0];
    const float* W_qkv = (const float*)d_in[1];
    const float* b_qkv = (const float*)d_in[2];
    const float* W_out = (const float*)d_in[3];
    const float* b_out = (const float*)d_in[4];
    float* out = (float*)d_out;

    float *qkv = nullptr, *attn = nullptr, *wqkv_t = nullptr, *wout_t = nullptr;
    cudaGetSymbolAddress((void**)&qkv,    g_qkv);
    cudaGetSymbolAddress((void**)&attn,   g_attn);
    cudaGetSymbolAddress((void**)&wqkv_t, g_wqkv_t);
    cudaGetSymbolAddress((void**)&wout_t, g_wout_t);

    cudaFuncSetAttribute(attn_mma_kernel,
                         cudaFuncAttributeMaxDynamicSharedMemorySize, ATTN_SMEM);

    // 0) Transpose weights to K-major
    {
        dim3 blk(32, 8);
        transpose_kernel<<<dim3(C3 / 32, CC / 32), blk>>>(W_qkv, wqkv_t, CC, C3);
        transpose_kernel<<<dim3(CC / 32, CC / 32), blk>>>(W_out, wout_t, CC, CC);
    }

    // 1) QKV projection (tf32 mma.sync)
    {
        dim3 grid(C3 / 128, MROWS / 128);
        gemm_mma_tf32<<<grid, 256>>>(x, wqkv_t, b_qkv, qkv, MROWS, C3, CC);
    }

    // 2) Causal attention (tf32 mma.sync flash attention)
    {
        dim3 grid(TT / 128, HH, BB);
        attn_mma_kernel<<<grid, 256, ATTN_SMEM>>>(qkv, attn);
    }

    // 3) Output projection (tf32 mma.sync)
    {
        dim3 grid(CC / 128, MROWS / 128);
        gemm_mma_tf32<<<grid, 256>>>(attn, wout_t, b_out, out, MROWS, CC, CC);
    }
}